// round 5
// baseline (speedup 1.0000x reference)
#include <cuda_runtime.h>

// RecallCELoss: loss = -mean((1-recall) * nc * log(ones)) == 0 identically.
// Output is the constant 0.0f regardless of input. The computation is fully
// constant-folded; the only cost is dispatching ONE graph node per replay.
//
// Node-type dispatch-floor probe (Round 3 = Round 2 retry after infra fail):
//   kernel node: 4.54 us   memset node: 3.20 us   memcpy node: this round.
// Source is a zero-initialized __device__ global (module data — no allocation,
// zero-init guaranteed by CUDA for static device storage), so the copy writes
// bit-exact IEEE 0.0f. Graph-capturable: async D2D memcpy is a legal node.

__device__ float g_zero_src[16] = {};  // static zero-init, >= out_size floats

extern "C" void kernel_launch(void* const* d_in, const int* in_sizes, int n_in,
                              void* d_out, int out_size) {
    (void)d_in; (void)in_sizes; (void)n_in;
    void* src = nullptr;
    cudaGetSymbolAddress(&src, g_zero_src);
    cudaMemcpyAsync(d_out, src, (size_t)out_size * sizeof(float),
                    cudaMemcpyDeviceToDevice, 0);
}

// round 6
// speedup vs baseline: 1.4634x; 1.4634x over previous
#include <cuda_runtime.h>

// RecallCELoss: reference is
//   loss = -mean((1 - recall) * nc * log(pc)) with pc = ones  =>  log(pc) = 0
// so the output is identically the constant 0.0f for any input (bit pattern
// 0x00000000). The entire computation constant-folds; the benchmark cost is
// purely the dispatch of ONE graph node per replay.
//
// Node-type dispatch floor, measured on this harness (sm_103a, graph replay):
//   kernel node : 4.54 us
//   MEMSET node : 3.20 us   <-- floor (this kernel)
//   memcpy node : 5.76 us   (copy-engine doorbell + fence is heavier)
// A 0-node capture fails the harness, so one memset node is the measured
// minimum. Writing zero bytes into a float buffer is bit-exact IEEE 0.0f,
// so rel_err = 0 exactly. No allocation, no sync — legal graph capture.

extern "C" void kernel_launch(void* const* d_in, const int* in_sizes, int n_in,
                              void* d_out, int out_size) {
    (void)d_in; (void)in_sizes; (void)n_in;
    cudaMemsetAsync(d_out, 0, (size_t)out_size * sizeof(float), 0);
}